// round 17
// baseline (speedup 1.0000x reference)
#include <cuda_runtime.h>
#include <math.h>
#include <stdint.h>

// ---------------- problem constants ----------------
#define BQ   16
#define NPTS 4096
#define MTOT (BQ*NPTS)          // 65536 points
#define FW   56                 // fmap H=W
#define PS   8

// ---------------- scratch (device globals; no allocation) ----------------
__device__ float d_pe   [MTOT*64];          // positional embedding, K padded 48->64 (tf32-rounded)
__device__ float d_lw1p [256*64];           // lw1 zero-padded to K=64 (tf32-rounded)
__device__ float d_lw2t [256*256];          // lw2 tf32-rounded
__device__ float d_hw1t [512*576];          // hw1 tf32-rounded
__device__ float d_pf1  [MTOT*256];         // after MLP layer 1 (gelu, tf32-rounded)
__device__ float d_fused[MTOT*576];         // [pf(256) | patches(256) | gc(64)] (tf32-rounded)
__device__ float d_h    [MTOT*512];         // head hidden (gelu, fp32)
__device__ float d_f1   [BQ*16*112*112];
__device__ float d_f2   [BQ*32*56*56];
__device__ float d_fmap [BQ*4*56*56];
__device__ float d_g1   [BQ*4*112*112];
__device__ float d_g2   [BQ*8*56*56];
__device__ float d_g3   [BQ*16*28*28];
__device__ float d_g4   [BQ*32*14*14];
__device__ float d_g5   [BQ*64*7*7];
__device__ float d_gc   [BQ*64];

// ---------------- helpers ----------------
__device__ __forceinline__ float gelu_tanh(float x) {
    const float c0 = 0.7978845608028654f;   // sqrt(2/pi)
    float x3 = x * x * x;
    float t  = tanhf(c0 * (x + 0.044715f * x3));
    return 0.5f * x * (1.0f + t);
}

__device__ __forceinline__ float tf32r(float x) {
    float y;
    asm("cvt.rna.tf32.f32 %0, %1;" : "=f"(y) : "f"(x));
    return y;
}

__device__ __forceinline__ uint32_t smem_u32(const void* p) {
    uint32_t a;
    asm("{ .reg .u64 t; cvta.to.shared.u64 t, %1; cvt.u32.u64 %0, t; }" : "=r"(a) : "l"(p));
    return a;
}

__device__ __forceinline__ void mma_tf32(float* c, const float* a, const float* b) {
    asm volatile("mma.sync.aligned.m16n8k8.row.col.f32.tf32.tf32.f32 "
        "{%0,%1,%2,%3}, {%4,%5,%6,%7}, {%8,%9}, {%0,%1,%2,%3};"
        : "+f"(c[0]), "+f"(c[1]), "+f"(c[2]), "+f"(c[3])
        : "r"(__float_as_uint(a[0])), "r"(__float_as_uint(a[1])),
          "r"(__float_as_uint(a[2])), "r"(__float_as_uint(a[3])),
          "r"(__float_as_uint(b[0])), "r"(__float_as_uint(b[1])));
}

// ---------------- positional embedding (K padded to 64, tf32-rounded) ----------------
__global__ void embed_kernel(const float* __restrict__ points, float* __restrict__ pe) {
    int idx = blockIdx.x * blockDim.x + threadIdx.x;   // over MTOT*16
    if (idx >= MTOT * 16) return;
    int pt = idx >> 4, i = idx & 15;
    float4 v;
    if (i < 12) {
        float x = points[pt * 2 + 0];
        float y = points[pt * 2 + 1];
        float f = exp2f((float)i);
        float sx, cx, sy, cy;
        sincosf(f * x, &sx, &cx);
        sincosf(f * y, &sy, &cy);
        v = make_float4(tf32r(sx), tf32r(sy), tf32r(cx), tf32r(cy));
    } else {
        v = make_float4(0.f, 0.f, 0.f, 0.f);
    }
    ((float4*)pe)[pt * 16 + i] = v;
}

// pack lw1 [256,48] -> [256,64] zero padded, tf32-rounded
__global__ void pack_lw1(const float* __restrict__ lw1, float* __restrict__ out) {
    int idx = blockIdx.x * blockDim.x + threadIdx.x;
    if (idx >= 256 * 64) return;
    int n = idx >> 6, k = idx & 63;
    out[idx] = (k < 48) ? tf32r(lw1[n * 48 + k]) : 0.f;
}

__global__ void round_copy(const float* __restrict__ in, float* __restrict__ out, int n) {
    int idx = blockIdx.x * blockDim.x + threadIdx.x;
    if (idx < n) out[idx] = tf32r(in[idx]);
}

// ---------------- templated 3x3 conv + gelu ----------------
// grid.y = b*Cout + co (weights staged in smem once per block); grid.x covers spatial.
// Interior fast path: no per-tap bounds checks, fully unrolled -> FFMA with immediate offsets.
template<int CIN, int STRIDE>
__global__ void __launch_bounds__(256) conv_t(const float* __restrict__ in,
                                              const float* __restrict__ wt,
                                              const float* __restrict__ bias,
                                              float* __restrict__ out,
                                              int Cout, int Hin, int Win, int Hout, int Wout) {
    __shared__ float wsh[CIN * 9];
    const int bc = blockIdx.y;
    const int co = bc % Cout, b = bc / Cout;
    for (int i = threadIdx.x; i < CIN * 9; i += blockDim.x)
        wsh[i] = wt[co * CIN * 9 + i];
    __syncthreads();

    int sp = blockIdx.x * blockDim.x + threadIdx.x;
    if (sp >= Hout * Wout) return;
    int oy = sp / Wout, ox = sp % Wout;
    int iy0 = oy * STRIDE - 1, ix0 = ox * STRIDE - 1;
    const float* ip = in + (size_t)b * CIN * Hin * Win;
    const int HW = Hin * Win;
    float acc = bias[co];

    if (iy0 >= 0 && ix0 >= 0 && iy0 + 3 <= Hin && ix0 + 3 <= Win) {
        const float* p0 = ip + iy0 * Win + ix0;
        #pragma unroll
        for (int ci = 0; ci < CIN; ci++) {
            const float* p = p0 + ci * HW;
            const float* w = wsh + ci * 9;
            #pragma unroll
            for (int ky = 0; ky < 3; ky++) {
                acc += p[ky * Win + 0] * w[ky * 3 + 0];
                acc += p[ky * Win + 1] * w[ky * 3 + 1];
                acc += p[ky * Win + 2] * w[ky * 3 + 2];
            }
        }
    } else {
        #pragma unroll
        for (int ci = 0; ci < CIN; ci++) {
            const float* p = ip + ci * HW;
            const float* w = wsh + ci * 9;
            #pragma unroll
            for (int ky = 0; ky < 3; ky++) {
                int iy = iy0 + ky;
                if (iy < 0 || iy >= Hin) continue;
                const float* row = p + iy * Win;
                #pragma unroll
                for (int kx = 0; kx < 3; kx++) {
                    int ix = ix0 + kx;
                    if (ix < 0 || ix >= Win) continue;
                    acc += row[ix] * w[ky * 3 + kx];
                }
            }
        }
    }
    out[(size_t)bc * Hout * Wout + sp] = gelu_tanh(acc);
}

// ---------------- global mean over 7x7 ----------------
__global__ void gmean_kernel(const float* __restrict__ g5, float* __restrict__ gc) {
    int idx = blockIdx.x * blockDim.x + threadIdx.x;   // BQ*64
    if (idx >= BQ * 64) return;
    const float* p = g5 + (size_t)idx * 49;
    float s = 0.f;
    #pragma unroll
    for (int i = 0; i < 49; i++) s += p[i];
    gc[idx] = s / 49.0f;
}

// ---------------- bilinear patch gather + gc broadcast into fused (tf32-rounded) ----------------
__global__ void patch_kernel(const float* __restrict__ points, const float* __restrict__ fmap,
                             const float* __restrict__ gc, float* __restrict__ fused) {
    int p = blockIdx.x * 4 + (threadIdx.x >> 6);
    int t = threadIdx.x & 63;
    int b = p >> 12;
    float px = points[p * 2 + 0];
    float py = points[p * 2 + 1];
    int i = t >> 3, j = t & 7;

    const float step = 2.0f / 55.0f;
    float gx = (px * 2.0f - 1.0f) + ((float)i - 3.5f) * step;
    float gy = (py * 2.0f - 1.0f) + ((float)j - 3.5f) * step;
    float ix = (gx + 1.0f) * 0.5f * 55.0f;
    float iy = (gy + 1.0f) * 0.5f * 55.0f;
    float x0f = floorf(ix), y0f = floorf(iy);
    int x0 = (int)x0f, y0 = (int)y0f;
    int x1 = x0 + 1,  y1 = y0 + 1;
    float wx1 = ix - x0f, wx0 = 1.0f - wx1;
    float wy1 = iy - y0f, wy0 = 1.0f - wy1;

    bool vx0 = (x0 >= 0) && (x0 < FW), vx1 = (x1 >= 0) && (x1 < FW);
    bool vy0 = (y0 >= 0) && (y0 < FW), vy1 = (y1 >= 0) && (y1 < FW);
    int cx0 = min(max(x0, 0), FW - 1), cx1 = min(max(x1, 0), FW - 1);
    int cy0 = min(max(y0, 0), FW - 1), cy1 = min(max(y1, 0), FW - 1);
    float w00 = (vx0 && vy0) ? wx0 * wy0 : 0.f;
    float w10 = (vx1 && vy0) ? wx1 * wy0 : 0.f;
    float w01 = (vx0 && vy1) ? wx0 * wy1 : 0.f;
    float w11 = (vx1 && vy1) ? wx1 * wy1 : 0.f;
    int i00 = cy0 * FW + cx0, i10 = cy0 * FW + cx1;
    int i01 = cy1 * FW + cx0, i11 = cy1 * FW + cx1;

    float* orow = fused + (size_t)p * 576;
    #pragma unroll
    for (int c = 0; c < 4; c++) {
        const float* f = fmap + (size_t)(b * 4 + c) * (FW * FW);
        float v = w00 * f[i00] + w10 * f[i10] + w01 * f[i01] + w11 * f[i11];
        orow[256 + c * 64 + t] = tf32r(v);
    }
    orow[512 + t] = tf32r(gc[b * 64 + t]);
}

// ---------------- tf32 mma.sync GEMM-NT, CTA tile 128x256 ----------------
// C[m,n] = sum_k A[m,k]*W[n,k] + bias[n] (+gelu, +tf32 round).
// 512 threads = 16 warps (2M x 8N), warp tile 64x32 (4x4 m16n8k8 per k8-step), BK=32.
// Smem [rows][36] pad-4 -> fragment LDS bank = lane%32, conflict-free.
// Each loader thread owns a 16-float half-row per stage -> FOUR 16B cp.asyncs (bug fixed).
#define SMPAD 36
#define A_STAGE_F (128 * SMPAD)
#define B_STAGE_F (256 * SMPAD)
#define GEMM_SMEM_BYTES ((2 * A_STAGE_F + 2 * B_STAGE_F) * 4)

template<bool DOGELU, bool ROUND>
__global__ void __launch_bounds__(512) mma_gemm(const float* __restrict__ A,
                                                const float* __restrict__ W,
                                                const float* __restrict__ bias,
                                                float* __restrict__ C,
                                                int K, int ldc) {
    extern __shared__ float sm[];
    float* As = sm;                       // [2][128][SMPAD]
    float* Bs = sm + 2 * A_STAGE_F;       // [2][256][SMPAD]
    const uint32_t uAs = smem_u32(As), uBs = smem_u32(Bs);

    const int tid  = threadIdx.x;
    const int lane = tid & 31, wid = tid >> 5;
    const int wm = wid >> 3, wn = wid & 7;       // 2 x 8 warps
    const int bm = blockIdx.y << 7, bn = blockIdx.x << 8;

    // loaders: each thread covers one (row, 16-float half) per matrix per stage
    const int arow = tid >> 1;                    // A: threads 0..255 -> rows 0..127
    const int brow = tid >> 1;                    // B: all 512 -> rows 0..255
    const int pcol = (tid & 1) << 4;              // 0 or 16 floats
    const float* apg = A + (size_t)(bm + arow) * K + pcol;
    const float* wpg = W + (size_t)(bn + brow) * K + pcol;
    const uint32_t sA_off = (uint32_t)(arow * SMPAD + pcol) * 4u;
    const uint32_t sB_off = (uint32_t)(brow * SMPAD + pcol) * 4u;

    const int S = K >> 5;

    auto prefetch = [&](int s, int buf) {
        if (tid < 256) {
            uint32_t da = uAs + (uint32_t)buf * (A_STAGE_F * 4u) + sA_off;
            const float* ap = apg + s * 32;
            #pragma unroll
            for (int q = 0; q < 4; q++)
                asm volatile("cp.async.cg.shared.global [%0], [%1], 16;"
                             :: "r"(da + q * 16u), "l"(ap + q * 4));
        }
        {
            uint32_t db = uBs + (uint32_t)buf * (B_STAGE_F * 4u) + sB_off;
            const float* wp = wpg + s * 32;
            #pragma unroll
            for (int q = 0; q < 4; q++)
                asm volatile("cp.async.cg.shared.global [%0], [%1], 16;"
                             :: "r"(db + q * 16u), "l"(wp + q * 4));
        }
        asm volatile("cp.async.commit_group;" ::: "memory");
    };

    float acc[4][4][4];
    #pragma unroll
    for (int i = 0; i < 4; i++)
        #pragma unroll
        for (int j = 0; j < 4; j++)
            #pragma unroll
            for (int q = 0; q < 4; q++) acc[i][j][q] = 0.f;

    prefetch(0, 0);
    if (S > 1) prefetch(1, 1);

    const int g4 = lane >> 2;          // 0..7
    const int t4 = lane & 3;           // 0..3

    for (int s = 0; s < S; s++) {
        if (s + 1 < S) { asm volatile("cp.async.wait_group 1;" ::: "memory"); }
        else           { asm volatile("cp.async.wait_group 0;" ::: "memory"); }
        __syncthreads();

        const float* as = As + (s & 1) * A_STAGE_F;
        const float* bs = Bs + (s & 1) * B_STAGE_F;
        #pragma unroll
        for (int kk = 0; kk < 4; kk++) {
            const int c0 = kk * 8 + t4;
            float ar[4][4];
            #pragma unroll
            for (int mt = 0; mt < 4; mt++) {
                int r = wm * 64 + mt * 16 + g4;
                ar[mt][0] = as[r * SMPAD + c0];
                ar[mt][1] = as[(r + 8) * SMPAD + c0];
                ar[mt][2] = as[r * SMPAD + c0 + 4];
                ar[mt][3] = as[(r + 8) * SMPAD + c0 + 4];
            }
            float br[4][2];
            #pragma unroll
            for (int nt = 0; nt < 4; nt++) {
                int n = wn * 32 + nt * 8 + g4;
                br[nt][0] = bs[n * SMPAD + c0];
                br[nt][1] = bs[n * SMPAD + c0 + 4];
            }
            #pragma unroll
            for (int mt = 0; mt < 4; mt++)
                #pragma unroll
                for (int nt = 0; nt < 4; nt++)
                    mma_tf32(acc[mt][nt], ar[mt], br[nt]);
        }
        __syncthreads();
        if (s + 2 < S) prefetch(s + 2, s & 1);
    }

    // epilogue
    #pragma unroll
    for (int nt = 0; nt < 4; nt++) {
        int col = bn + wn * 32 + nt * 8 + t4 * 2;
        float b0 = bias[col], b1 = bias[col + 1];
        #pragma unroll
        for (int mt = 0; mt < 4; mt++) {
            int row = bm + wm * 64 + mt * 16 + g4;
            float v0 = acc[mt][nt][0] + b0;
            float v1 = acc[mt][nt][1] + b1;
            float v2 = acc[mt][nt][2] + b0;
            float v3 = acc[mt][nt][3] + b1;
            if (DOGELU) { v0 = gelu_tanh(v0); v1 = gelu_tanh(v1); v2 = gelu_tanh(v2); v3 = gelu_tanh(v3); }
            if (ROUND)  { v0 = tf32r(v0); v1 = tf32r(v1); v2 = tf32r(v2); v3 = tf32r(v3); }
            *(float2*)(C + (size_t)row * ldc + col)       = make_float2(v0, v1);
            *(float2*)(C + (size_t)(row + 8) * ldc + col) = make_float2(v2, v3);
        }
    }
}

// ---------------- final GEMV: out[m] = dot(h[m,:512], hw2) + hb2 ----------------
__global__ void gemv_out(const float* __restrict__ h, const float* __restrict__ w2,
                         const float* __restrict__ b2, float* __restrict__ out) {
    int m = blockIdx.x * 8 + (threadIdx.x >> 5);
    int lane = threadIdx.x & 31;
    const float4* hp = (const float4*)(h + (size_t)m * 512);
    const float4* wp = (const float4*)w2;
    float s = 0.f;
    #pragma unroll
    for (int it = 0; it < 4; it++) {
        float4 a = hp[lane + it * 32];
        float4 b = wp[lane + it * 32];
        s += a.x * b.x + a.y * b.y + a.z * b.z + a.w * b.w;
    }
    #pragma unroll
    for (int o = 16; o > 0; o >>= 1) s += __shfl_xor_sync(0xFFFFFFFFu, s, o);
    if (lane == 0) out[m] = s + b2[0];
}

// ---------------- launch ----------------
extern "C" void kernel_launch(void* const* d_in, const int* in_sizes, int n_in,
                              void* d_out, int out_size) {
    const float* points = (const float*)d_in[0];
    const float* images = (const float*)d_in[1];
    const float* pw1 = (const float*)d_in[2];  const float* pb1 = (const float*)d_in[3];
    const float* pw2 = (const float*)d_in[4];  const float* pb2 = (const float*)d_in[5];
    const float* pw3 = (const float*)d_in[6];  const float* pb3 = (const float*)d_in[7];
    const float* gw1 = (const float*)d_in[8];  const float* gb1 = (const float*)d_in[9];
    const float* gw2 = (const float*)d_in[10]; const float* gb2 = (const float*)d_in[11];
    const float* gw3 = (const float*)d_in[12]; const float* gb3 = (const float*)d_in[13];
    const float* gw4 = (const float*)d_in[14]; const float* gb4 = (const float*)d_in[15];
    const float* gw5 = (const float*)d_in[16]; const float* gb5 = (const float*)d_in[17];
    const float* lw1 = (const float*)d_in[18]; const float* lb1 = (const float*)d_in[19];
    const float* lw2 = (const float*)d_in[20]; const float* lb2 = (const float*)d_in[21];
    const float* hw1 = (const float*)d_in[22]; const float* hb1 = (const float*)d_in[23];
    const float* hw2 = (const float*)d_in[24]; const float* hb2 = (const float*)d_in[25];
    float* out = (float*)d_out;

    float *pe, *lw1p, *lw2t, *hw1t, *pf1, *fused, *h;
    float *f1, *f2, *fmap, *g1, *g2, *g3, *g4, *g5, *gc;
    cudaGetSymbolAddress((void**)&pe,    d_pe);
    cudaGetSymbolAddress((void**)&lw1p,  d_lw1p);
    cudaGetSymbolAddress((void**)&lw2t,  d_lw2t);
    cudaGetSymbolAddress((void**)&hw1t,  d_hw1t);
    cudaGetSymbolAddress((void**)&pf1,   d_pf1);
    cudaGetSymbolAddress((void**)&fused, d_fused);
    cudaGetSymbolAddress((void**)&h,     d_h);
    cudaGetSymbolAddress((void**)&f1,    d_f1);
    cudaGetSymbolAddress((void**)&f2,    d_f2);
    cudaGetSymbolAddress((void**)&fmap,  d_fmap);
    cudaGetSymbolAddress((void**)&g1,    d_g1);
    cudaGetSymbolAddress((void**)&g2,    d_g2);
    cudaGetSymbolAddress((void**)&g3,    d_g3);
    cudaGetSymbolAddress((void**)&g4,    d_g4);
    cudaGetSymbolAddress((void**)&g5,    d_g5);
    cudaGetSymbolAddress((void**)&gc,    d_gc);

    cudaFuncSetAttribute(mma_gemm<true, true>,   cudaFuncAttributeMaxDynamicSharedMemorySize, GEMM_SMEM_BYTES);
    cudaFuncSetAttribute(mma_gemm<false, true>,  cudaFuncAttributeMaxDynamicSharedMemorySize, GEMM_SMEM_BYTES);
    cudaFuncSetAttribute(mma_gemm<true, false>,  cudaFuncAttributeMaxDynamicSharedMemorySize, GEMM_SMEM_BYTES);

    const int T = 256;
    auto blocks = [](int total) { return (total + 255) / 256; };

    // inputs prep (tf32-rounded operands)
    embed_kernel<<<blocks(MTOT * 16), T>>>(points, pe);
    pack_lw1<<<blocks(256 * 64), T>>>(lw1, lw1p);
    round_copy<<<blocks(256 * 256), T>>>(lw2, lw2t, 256 * 256);
    round_copy<<<blocks(512 * 576), T>>>(hw1, hw1t, 512 * 576);

    // plane encoder (templated convs: grid.y = b*Cout + co)
    conv_t<3, 2><<<dim3(blocks(112 * 112), BQ * 16), T>>>(images, pw1, pb1, f1, 16, 224, 224, 112, 112);
    conv_t<16, 2><<<dim3(blocks(56 * 56), BQ * 32), T>>>(f1, pw2, pb2, f2, 32, 112, 112, 56, 56);
    conv_t<32, 1><<<dim3(blocks(56 * 56), BQ * 4),  T>>>(f2, pw3, pb3, fmap, 4, 56, 56, 56, 56);

    // global encoder
    conv_t<3, 2><<<dim3(blocks(112 * 112), BQ * 4),  T>>>(images, gw1, gb1, g1, 4, 224, 224, 112, 112);
    conv_t<4, 2><<<dim3(blocks(56 * 56), BQ * 8),    T>>>(g1, gw2, gb2, g2, 8, 112, 112, 56, 56);
    conv_t<8, 2><<<dim3(blocks(28 * 28), BQ * 16),   T>>>(g2, gw3, gb3, g3, 16, 56, 56, 28, 28);
    conv_t<16, 2><<<dim3(blocks(14 * 14), BQ * 32),  T>>>(g3, gw4, gb4, g4, 32, 28, 28, 14, 14);
    conv_t<32, 2><<<dim3(blocks(7 * 7), BQ * 64),    T>>>(g4, gw5, gb5, g5, 64, 14, 14, 7, 7);
    gmean_kernel<<<blocks(BQ * 64), T>>>(g5, gc);

    // point MLP (tf32 tensor cores, BN=256 -> single N block)
    mma_gemm<true,  true ><<<dim3(1, 512), 512, GEMM_SMEM_BYTES>>>(pe,   lw1p, lb1, pf1,   64,  256);
    mma_gemm<false, true ><<<dim3(1, 512), 512, GEMM_SMEM_BYTES>>>(pf1,  lw2t, lb2, fused, 256, 576);

    // patches + gc into fused[:, 256:576]
    patch_kernel<<<MTOT / 4, 256>>>(points, fmap, gc, fused);

    // head (tf32 tensor cores, N=512 -> 2 N blocks)
    mma_gemm<true,  false><<<dim3(2, 512), 512, GEMM_SMEM_BYTES>>>(fused, hw1t, hb1, h, 576, 512);

    // out = h @ hw2^T + hb2 (fp32 GEMV)
    gemv_out<<<MTOT / 8, 256>>>(h, hw2, hb2, out);

    (void)in_sizes; (void)n_in; (void)out_size;
}